// round 1
// baseline (speedup 1.0000x reference)
#include <cuda_runtime.h>

#define K_B 4
#define K_S 2048
#define K_D 1024
#define K_H 16
#define K_DH 64
#define K_ROWS (K_B * K_S)   // 8192

// Scratch (device globals: allocation-free per harness rules)
__device__ float g_Q[K_ROWS * K_D];
__device__ float g_K[K_ROWS * K_D];
__device__ float g_V[K_ROWS * K_D];
__device__ float g_C[K_ROWS * K_D];

// ---------------------------------------------------------------------------
// GEMM: out[i][j] = sum_k x[i][k] * W[j][k] + bias[j]
// x: [K_ROWS, K_D], W: [K_D, K_D] row-major (torch Linear weight), out: [K_ROWS, K_D]
// Tile: BM=128, BN=128, BK=16; 256 threads; 8x8 per thread.
// ---------------------------------------------------------------------------
__global__ __launch_bounds__(256) void gemm_xwt_kernel(
    const float* __restrict__ x, const float* __restrict__ W,
    const float* __restrict__ bias, float* __restrict__ out)
{
    const int BM = 128, BN = 128, BK = 16;
    __shared__ float As[16][BM + 4];   // As[k][m], row stride 132 floats (16B aligned)
    __shared__ float Bs[16][BN + 4];   // Bs[k][n]

    const int tid = threadIdx.x;
    const int tx = tid & 15;           // col group
    const int ty = tid >> 4;           // row group
    const int rowBase = blockIdx.y * BM;
    const int colBase = blockIdx.x * BN;

    float acc[8][8];
    #pragma unroll
    for (int i = 0; i < 8; i++)
        #pragma unroll
        for (int j = 0; j < 8; j++) acc[i][j] = 0.f;

    for (int k0 = 0; k0 < K_D; k0 += BK) {
        // Load A tile (128 x 16) -> As[k][m] transposed
        #pragma unroll
        for (int it = 0; it < 2; it++) {
            int li = tid + it * 256;           // 0..511
            int m  = li >> 2;                  // 0..127
            int k  = (li & 3) * 4;             // 0,4,8,12
            float4 v = *(const float4*)&x[(size_t)(rowBase + m) * K_D + k0 + k];
            As[k + 0][m] = v.x; As[k + 1][m] = v.y;
            As[k + 2][m] = v.z; As[k + 3][m] = v.w;
        }
        // Load B tile (128 x 16) -> Bs[k][n]
        #pragma unroll
        for (int it = 0; it < 2; it++) {
            int li = tid + it * 256;
            int n  = li >> 2;
            int k  = (li & 3) * 4;
            float4 v = *(const float4*)&W[(size_t)(colBase + n) * K_D + k0 + k];
            Bs[k + 0][n] = v.x; Bs[k + 1][n] = v.y;
            Bs[k + 2][n] = v.z; Bs[k + 3][n] = v.w;
        }
        __syncthreads();

        #pragma unroll
        for (int k = 0; k < BK; k++) {
            float a[8], b[8];
            float4 a0 = *(const float4*)&As[k][ty * 8];
            float4 a1 = *(const float4*)&As[k][ty * 8 + 4];
            float4 b0 = *(const float4*)&Bs[k][tx * 8];
            float4 b1 = *(const float4*)&Bs[k][tx * 8 + 4];
            a[0]=a0.x; a[1]=a0.y; a[2]=a0.z; a[3]=a0.w;
            a[4]=a1.x; a[5]=a1.y; a[6]=a1.z; a[7]=a1.w;
            b[0]=b0.x; b[1]=b0.y; b[2]=b0.z; b[3]=b0.w;
            b[4]=b1.x; b[5]=b1.y; b[6]=b1.z; b[7]=b1.w;
            #pragma unroll
            for (int i = 0; i < 8; i++)
                #pragma unroll
                for (int j = 0; j < 8; j++)
                    acc[i][j] += a[i] * b[j];
        }
        __syncthreads();
    }

    #pragma unroll
    for (int i = 0; i < 8; i++) {
        int r = rowBase + ty * 8 + i;
        #pragma unroll
        for (int j = 0; j < 8; j += 4) {
            int c = colBase + tx * 8 + j;
            float4 v;
            v.x = acc[i][j + 0] + bias[c + 0];
            v.y = acc[i][j + 1] + bias[c + 1];
            v.z = acc[i][j + 2] + bias[c + 2];
            v.w = acc[i][j + 3] + bias[c + 3];
            *(float4*)&out[(size_t)r * K_D + c] = v;
        }
    }
}

// ---------------------------------------------------------------------------
// Flash attention (fp32, online softmax).
// Grid: (B*H, S/BR). Block: 256 threads.
// BR=64 query rows, BC=32 key rows per tile, Dh=64.
// Q/K/V/C layout: [B, S, D] with head h at columns h*64 .. h*64+63.
// ---------------------------------------------------------------------------
#define BR 64
#define BC 32
#define QK_STRIDE 68   // 68*4B = 272 = 16B-aligned row stride
#define SS_STRIDE 36   // 36*4B = 144 = 16B-aligned

__global__ __launch_bounds__(256) void flash_attn_kernel(
    const float* __restrict__ Q, const float* __restrict__ K,
    const float* __restrict__ V, float* __restrict__ O)
{
    __shared__ float Qs[BR][QK_STRIDE];
    __shared__ float Ks[BC][QK_STRIDE];
    __shared__ float Vs[BC][QK_STRIDE];
    __shared__ float Ss[BR][SS_STRIDE];
    __shared__ float sm[BR], sl[BR], salpha[BR];

    const int tid = threadIdx.x;
    const int bh = blockIdx.x;
    const int b = bh / K_H, h = bh % K_H;
    const int qbase = blockIdx.y * BR;
    const size_t base = (size_t)b * K_S * K_D + (size_t)h * K_DH;

    const int tx = tid & 15;   // 16 col groups
    const int ty = tid >> 4;   // 16 row groups (4 rows each)
    const float scale = 0.125f;  // 1/sqrt(64)

    // Load Q tile (64 x 64): 1024 float4, 4 per thread
    #pragma unroll
    for (int it = 0; it < 4; it++) {
        int li = tid + it * 256;
        int r = li >> 4;
        int k = (li & 15) * 4;
        float4 v = *(const float4*)&Q[base + (size_t)(qbase + r) * K_D + k];
        Qs[r][k] = v.x; Qs[r][k + 1] = v.y; Qs[r][k + 2] = v.z; Qs[r][k + 3] = v.w;
    }
    if (tid < BR) { sm[tid] = -1e30f; sl[tid] = 0.f; }

    float acc[4][4];   // rows ty*4+i, dims tx*4+j
    #pragma unroll
    for (int i = 0; i < 4; i++)
        #pragma unroll
        for (int j = 0; j < 4; j++) acc[i][j] = 0.f;

    __syncthreads();

    for (int j0 = 0; j0 < K_S; j0 += BC) {
        // Load K/V tiles (32 x 64 each): 512 float4 each, 2 per thread
        #pragma unroll
        for (int it = 0; it < 2; it++) {
            int li = tid + it * 256;
            int c = li >> 4;
            int k = (li & 15) * 4;
            float4 kv = *(const float4*)&K[base + (size_t)(j0 + c) * K_D + k];
            Ks[c][k] = kv.x; Ks[c][k + 1] = kv.y; Ks[c][k + 2] = kv.z; Ks[c][k + 3] = kv.w;
            float4 vv = *(const float4*)&V[base + (size_t)(j0 + c) * K_D + k];
            Vs[c][k] = vv.x; Vs[c][k + 1] = vv.y; Vs[c][k + 2] = vv.z; Vs[c][k + 3] = vv.w;
        }
        __syncthreads();

        // S = Q K^T * scale : thread computes 4 rows x 2 cols, vectorized over k
        {
            const int c0 = tx * 2;
            float s0[4] = {0.f, 0.f, 0.f, 0.f};
            float s1[4] = {0.f, 0.f, 0.f, 0.f};
            #pragma unroll
            for (int k0 = 0; k0 < K_DH; k0 += 4) {
                float4 k0v = *(const float4*)&Ks[c0][k0];
                float4 k1v = *(const float4*)&Ks[c0 + 1][k0];
                #pragma unroll
                for (int i = 0; i < 4; i++) {
                    float4 q = *(const float4*)&Qs[ty * 4 + i][k0];
                    s0[i] += q.x * k0v.x + q.y * k0v.y + q.z * k0v.z + q.w * k0v.w;
                    s1[i] += q.x * k1v.x + q.y * k1v.y + q.z * k1v.z + q.w * k1v.w;
                }
            }
            #pragma unroll
            for (int i = 0; i < 4; i++) {
                float2 sv = make_float2(s0[i] * scale, s1[i] * scale);
                *(float2*)&Ss[ty * 4 + i][c0] = sv;
            }
        }
        __syncthreads();

        // Online softmax: 4 threads per row, 8 cols each
        {
            const int row = tid >> 2;
            const int seg = tid & 3;
            float mx = -1e30f;
            #pragma unroll
            for (int c = 0; c < 8; c++) mx = fmaxf(mx, Ss[row][seg * 8 + c]);
            mx = fmaxf(mx, __shfl_xor_sync(0xffffffffu, mx, 1));
            mx = fmaxf(mx, __shfl_xor_sync(0xffffffffu, mx, 2));
            float mold = sm[row];
            float mnew = fmaxf(mold, mx);
            float sum = 0.f;
            #pragma unroll
            for (int c = 0; c < 8; c++) {
                float p = __expf(Ss[row][seg * 8 + c] - mnew);
                Ss[row][seg * 8 + c] = p;
                sum += p;
            }
            sum += __shfl_xor_sync(0xffffffffu, sum, 1);
            sum += __shfl_xor_sync(0xffffffffu, sum, 2);
            if (seg == 0) {
                float alpha = __expf(mold - mnew);
                salpha[row] = alpha;
                sm[row] = mnew;
                sl[row] = sl[row] * alpha + sum;
            }
        }
        __syncthreads();

        // Rescale accumulators, then O += P @ V (thread: 4 rows x 4 dims)
        #pragma unroll
        for (int i = 0; i < 4; i++) {
            float al = salpha[ty * 4 + i];
            #pragma unroll
            for (int j = 0; j < 4; j++) acc[i][j] *= al;
        }
        #pragma unroll
        for (int c0 = 0; c0 < BC; c0 += 4) {
            float4 p[4];
            #pragma unroll
            for (int i = 0; i < 4; i++)
                p[i] = *(const float4*)&Ss[ty * 4 + i][c0];
            #pragma unroll
            for (int cc = 0; cc < 4; cc++) {
                float4 v = *(const float4*)&Vs[c0 + cc][tx * 4];
                #pragma unroll
                for (int i = 0; i < 4; i++) {
                    float pi = (cc == 0) ? p[i].x : (cc == 1) ? p[i].y : (cc == 2) ? p[i].z : p[i].w;
                    acc[i][0] += pi * v.x;
                    acc[i][1] += pi * v.y;
                    acc[i][2] += pi * v.z;
                    acc[i][3] += pi * v.w;
                }
            }
        }
        __syncthreads();
    }

    // Epilogue: normalize by l, write context
    #pragma unroll
    for (int i = 0; i < 4; i++) {
        int r = ty * 4 + i;
        float inv = 1.0f / sl[r];
        float4 v;
        v.x = acc[i][0] * inv;
        v.y = acc[i][1] * inv;
        v.z = acc[i][2] * inv;
        v.w = acc[i][3] * inv;
        *(float4*)&O[base + (size_t)(qbase + r) * K_D + tx * 4] = v;
    }
}

// ---------------------------------------------------------------------------
extern "C" void kernel_launch(void* const* d_in, const int* in_sizes, int n_in,
                              void* d_out, int out_size)
{
    const float* query = (const float*)d_in[0];
    const float* key   = (const float*)d_in[1];
    const float* value = (const float*)d_in[2];
    const float* Wq    = (const float*)d_in[3];
    const float* bq    = (const float*)d_in[4];
    const float* Wk    = (const float*)d_in[5];
    const float* bk    = (const float*)d_in[6];
    const float* Wv    = (const float*)d_in[7];
    const float* bv    = (const float*)d_in[8];
    const float* Wo    = (const float*)d_in[9];
    const float* bo    = (const float*)d_in[10];
    float* out = (float*)d_out;

    float *gq, *gk, *gv, *gc;
    cudaGetSymbolAddress((void**)&gq, g_Q);
    cudaGetSymbolAddress((void**)&gk, g_K);
    cudaGetSymbolAddress((void**)&gv, g_V);
    cudaGetSymbolAddress((void**)&gc, g_C);

    dim3 gemm_grid(K_D / 128, K_ROWS / 128);   // (8, 64)
    gemm_xwt_kernel<<<gemm_grid, 256>>>(query, Wq, bq, gq);
    gemm_xwt_kernel<<<gemm_grid, 256>>>(key,   Wk, bk, gk);
    gemm_xwt_kernel<<<gemm_grid, 256>>>(value, Wv, bv, gv);

    dim3 attn_grid(K_B * K_H, K_S / BR);       // (64, 32)
    flash_attn_kernel<<<attn_grid, 256>>>(gq, gk, gv, gc);

    gemm_xwt_kernel<<<gemm_grid, 256>>>(gc, Wo, bo, out);
}

// round 2
// speedup vs baseline: 2.2921x; 2.2921x over previous
#include <cuda_runtime.h>

#define K_B 4
#define K_S 2048
#define K_D 1024
#define K_H 16
#define K_DH 64
#define K_ROWS (K_B * K_S)   // 8192

// Scratch (device globals: allocation-free per harness rules)
__device__ float g_Q[K_ROWS * K_D];
__device__ float g_K[K_ROWS * K_D];
__device__ float g_V[K_ROWS * K_D];
__device__ float g_C[K_ROWS * K_D];

// ---------------------------------------------------------------------------
// tf32 helpers
// ---------------------------------------------------------------------------
__device__ __forceinline__ unsigned f2tf(float f) {
    unsigned u;
    asm("cvt.rna.tf32.f32 %0, %1;" : "=r"(u) : "f"(f));
    return u;
}

__device__ __forceinline__ void mma_tf32(float* d, const uint4 a, const uint2 b) {
    asm volatile(
        "mma.sync.aligned.m16n8k8.row.col.f32.tf32.tf32.f32 "
        "{%0,%1,%2,%3}, {%4,%5,%6,%7}, {%8,%9}, {%0,%1,%2,%3};\n"
        : "+f"(d[0]), "+f"(d[1]), "+f"(d[2]), "+f"(d[3])
        : "r"(a.x), "r"(a.y), "r"(a.z), "r"(a.w), "r"(b.x), "r"(b.y));
}

// Fragment-layout smem index helpers (m16n8k8 tf32).
// A element (r within 16, c within 8): lane=(r&7)*4+(c&3), reg=(r>>3)+2*((c>>2)&1)
// B element (k within 8, n within 8):  lane=(n&7)*4+(k&3), reg=(k>>2)&1

// ---------------------------------------------------------------------------
// GEMM: out[i][j] = sum_k x[i][k] * W[j][k] + bias[j]   (x @ W^T + b)
// M=8192, N=1024, K=1024. BM=128, BN=128, BK=32, 256 threads (8 warps),
// warp tile 32x64. Operands stored in smem in mma-fragment layout (tf32).
// ---------------------------------------------------------------------------
__global__ __launch_bounds__(256) void gemm_tc(
    const float* __restrict__ x, const float* __restrict__ W,
    const float* __restrict__ bias, float* __restrict__ out)
{
    __shared__ unsigned As[8 * 4 * 32 * 4];   // [mt 8][kt 4][lane 32][reg 4] 16KB
    __shared__ unsigned Bs[16 * 4 * 32 * 2];  // [nt16][kt 4][lane 32][reg 2] 16KB

    const int tid  = threadIdx.x;
    const int lane = tid & 31;
    const int warp = tid >> 5;
    const int wm = warp >> 1;   // 0..3 : rows of 32
    const int wn = warp & 1;    // 0..1 : cols of 64
    const int rowBase = blockIdx.y * 128;
    const int colBase = blockIdx.x * 128;

    float acc[2][8][4];
    #pragma unroll
    for (int mi = 0; mi < 2; mi++)
        #pragma unroll
        for (int ni = 0; ni < 8; ni++)
            #pragma unroll
            for (int v = 0; v < 4; v++) acc[mi][ni][v] = 0.f;

    float4 pa[4], pb[4];
    #pragma unroll
    for (int i = 0; i < 4; i++) {
        int li = tid + i * 256;
        int m = li >> 3;
        int k = (li & 7) * 4;
        pa[i] = *(const float4*)&x[(size_t)(rowBase + m) * K_D + k];
        pb[i] = *(const float4*)&W[(size_t)(colBase + m) * K_D + k];
    }

    const uint4* As4 = (const uint4*)As;
    const uint2* Bs2 = (const uint2*)Bs;

    for (int k0 = 0; k0 < K_D; k0 += 32) {
        __syncthreads();   // previous compute done before overwrite
        #pragma unroll
        for (int i = 0; i < 4; i++) {
            int li = tid + i * 256;
            int m = li >> 3;
            int kk = (li & 7) * 4;
            float av[4] = {pa[i].x, pa[i].y, pa[i].z, pa[i].w};
            float bv[4] = {pb[i].x, pb[i].y, pb[i].z, pb[i].w};
            #pragma unroll
            for (int j = 0; j < 4; j++) {
                int k = kk + j;
                // A-frag store
                int ia = (((m >> 4) * 4 + (k >> 3)) * 32 + ((m & 7) * 4 + (k & 3))) * 4
                         + (((m >> 3) & 1) + 2 * ((k >> 2) & 1));
                As[ia] = f2tf(av[j]);
                // B-frag store (n = m index here)
                int ib = (((m >> 3) * 4 + (k >> 3)) * 32 + ((m & 7) * 4 + (k & 3))) * 2
                         + ((k >> 2) & 1);
                Bs[ib] = f2tf(bv[j]);
            }
        }
        __syncthreads();

        if (k0 + 32 < K_D) {
            #pragma unroll
            for (int i = 0; i < 4; i++) {
                int li = tid + i * 256;
                int m = li >> 3;
                int k = (li & 7) * 4;
                pa[i] = *(const float4*)&x[(size_t)(rowBase + m) * K_D + k0 + 32 + k];
                pb[i] = *(const float4*)&W[(size_t)(colBase + m) * K_D + k0 + 32 + k];
            }
        }

        #pragma unroll
        for (int kt = 0; kt < 4; kt++) {
            uint4 afr[2];
            #pragma unroll
            for (int mi = 0; mi < 2; mi++)
                afr[mi] = As4[((wm * 2 + mi) * 4 + kt) * 32 + lane];
            #pragma unroll
            for (int ni = 0; ni < 8; ni++) {
                uint2 bfr = Bs2[((wn * 8 + ni) * 4 + kt) * 32 + lane];
                #pragma unroll
                for (int mi = 0; mi < 2; mi++)
                    mma_tf32(acc[mi][ni], afr[mi], bfr);
            }
        }
    }

    // Epilogue: C frag rows lane>>2, lane>>2+8; cols (lane&3)*2, +1
    #pragma unroll
    for (int mi = 0; mi < 2; mi++) {
        int row0 = rowBase + (wm * 2 + mi) * 16 + (lane >> 2);
        #pragma unroll
        for (int ni = 0; ni < 8; ni++) {
            int col = colBase + (wn * 8 + ni) * 8 + (lane & 3) * 2;
            float b0 = __ldg(&bias[col]);
            float b1 = __ldg(&bias[col + 1]);
            float2 v0 = make_float2(acc[mi][ni][0] + b0, acc[mi][ni][1] + b1);
            float2 v1 = make_float2(acc[mi][ni][2] + b0, acc[mi][ni][3] + b1);
            *(float2*)&out[(size_t)row0 * K_D + col] = v0;
            *(float2*)&out[(size_t)(row0 + 8) * K_D + col] = v1;
        }
    }
}

// ---------------------------------------------------------------------------
// Flash attention, tf32 tensor cores.
// Grid: (B*H, S/128). Block: 256 threads (8 warps).
// Br=128 (16 rows per warp => softmax warp-local), Bc=64, Dh=64.
// Smem (dynamic, 96KB): Qs (A-frag), Ks (B-frag), Vts (B-frag), Ps (A-frag).
// ---------------------------------------------------------------------------
extern __shared__ unsigned smem_attn[];

__global__ __launch_bounds__(256) void flash_tc(
    const float* __restrict__ Q, const float* __restrict__ K,
    const float* __restrict__ V, float* __restrict__ O)
{
    unsigned* Qs  = smem_attn;              // [mt 8][kt 8][32][4] = 8192
    unsigned* Ks  = smem_attn + 8192;       // [nt 8][kt 8][32][2] = 4096
    unsigned* Vts = smem_attn + 12288;      // [nt 8][kt 8][32][2] = 4096
    unsigned* Ps  = smem_attn + 16384;      // [mt 8][kt 8][32][4] = 8192

    const int tid  = threadIdx.x;
    const int lane = tid & 31;
    const int warp = tid >> 5;

    const int bh = blockIdx.x;
    const int b = bh / K_H, h = bh % K_H;
    const int qbase = blockIdx.y * 128;
    const size_t base = (size_t)b * K_S * K_D + (size_t)h * K_DH;

    // Load Q tile (128 x 64) into A-frag layout (tf32)
    #pragma unroll
    for (int i = 0; i < 8; i++) {
        int li = tid + i * 256;
        int m = li >> 4;
        int k = (li & 15) * 4;
        float4 v = *(const float4*)&Q[base + (size_t)(qbase + m) * K_D + k];
        float qv[4] = {v.x, v.y, v.z, v.w};
        #pragma unroll
        for (int j = 0; j < 4; j++) {
            int kk = k + j;
            int ia = (((m >> 4) * 8 + (kk >> 3)) * 32 + ((m & 7) * 4 + (kk & 3))) * 4
                     + (((m >> 3) & 1) + 2 * ((kk >> 2) & 1));
            Qs[ia] = f2tf(qv[j]);
        }
    }

    float accO[8][4];
    #pragma unroll
    for (int ni = 0; ni < 8; ni++)
        #pragma unroll
        for (int v = 0; v < 4; v++) accO[ni][v] = 0.f;

    float m0 = -1e30f, m1 = -1e30f, l0 = 0.f, l1 = 0.f;
    const float scale = 0.125f;   // 1/sqrt(64)

    const uint4* Qs4 = (const uint4*)Qs;
    const uint2* Ks2 = (const uint2*)Ks;
    const uint2* Vt2 = (const uint2*)Vts;
    const uint4* Ps4 = (const uint4*)Ps;

    for (int jt = 0; jt < K_S; jt += 64) {
        __syncthreads();   // all warps done reading previous K/V
        // Load K (B-frag for QK: n=kv row, k=dim) and V (B-frag for PV: n=dim, k=kv row)
        #pragma unroll
        for (int i = 0; i < 4; i++) {
            int li = tid + i * 256;
            int n = li >> 4;           // kv row within tile (0..63)
            int k = (li & 15) * 4;     // dim
            float4 kv = *(const float4*)&K[base + (size_t)(jt + n) * K_D + k];
            float4 vv = *(const float4*)&V[base + (size_t)(jt + n) * K_D + k];
            float kvv[4] = {kv.x, kv.y, kv.z, kv.w};
            float vvv[4] = {vv.x, vv.y, vv.z, vv.w};
            #pragma unroll
            for (int j = 0; j < 4; j++) {
                int kk = k + j;   // dim index
                int ib = (((n >> 3) * 8 + (kk >> 3)) * 32 + ((n & 7) * 4 + (kk & 3))) * 2
                         + ((kk >> 2) & 1);
                Ks[ib] = f2tf(kvv[j]);
                int iv = (((kk >> 3) * 8 + (n >> 3)) * 32 + ((kk & 7) * 4 + (n & 3))) * 2
                         + ((n >> 2) & 1);
                Vts[iv] = f2tf(vvv[j]);
            }
        }
        __syncthreads();

        // S = Q K^T
        float accS[8][4];
        #pragma unroll
        for (int ni = 0; ni < 8; ni++)
            #pragma unroll
            for (int v = 0; v < 4; v++) accS[ni][v] = 0.f;

        #pragma unroll
        for (int kt = 0; kt < 8; kt++) {
            uint4 afr = Qs4[(warp * 8 + kt) * 32 + lane];
            #pragma unroll
            for (int ni = 0; ni < 8; ni++) {
                uint2 bfr = Ks2[(ni * 8 + kt) * 32 + lane];
                mma_tf32(accS[ni], afr, bfr);
            }
        }

        // scale + online softmax (rows r0=lane>>2, r1=r0+8; quad = 4 lanes/row)
        float mx0 = -1e30f, mx1 = -1e30f;
        #pragma unroll
        for (int ni = 0; ni < 8; ni++) {
            #pragma unroll
            for (int v = 0; v < 4; v++) accS[ni][v] *= scale;
            mx0 = fmaxf(mx0, fmaxf(accS[ni][0], accS[ni][1]));
            mx1 = fmaxf(mx1, fmaxf(accS[ni][2], accS[ni][3]));
        }
        mx0 = fmaxf(mx0, __shfl_xor_sync(0xffffffffu, mx0, 1));
        mx0 = fmaxf(mx0, __shfl_xor_sync(0xffffffffu, mx0, 2));
        mx1 = fmaxf(mx1, __shfl_xor_sync(0xffffffffu, mx1, 1));
        mx1 = fmaxf(mx1, __shfl_xor_sync(0xffffffffu, mx1, 2));

        float mn0 = fmaxf(m0, mx0);
        float mn1 = fmaxf(m1, mx1);
        float alpha0 = __expf(m0 - mn0);
        float alpha1 = __expf(m1 - mn1);
        m0 = mn0; m1 = mn1;

        float sum0 = 0.f, sum1 = 0.f;
        #pragma unroll
        for (int ni = 0; ni < 8; ni++) {
            accS[ni][0] = __expf(accS[ni][0] - mn0);
            accS[ni][1] = __expf(accS[ni][1] - mn0);
            accS[ni][2] = __expf(accS[ni][2] - mn1);
            accS[ni][3] = __expf(accS[ni][3] - mn1);
            sum0 += accS[ni][0] + accS[ni][1];
            sum1 += accS[ni][2] + accS[ni][3];
        }
        sum0 += __shfl_xor_sync(0xffffffffu, sum0, 1);
        sum0 += __shfl_xor_sync(0xffffffffu, sum0, 2);
        sum1 += __shfl_xor_sync(0xffffffffu, sum1, 1);
        sum1 += __shfl_xor_sync(0xffffffffu, sum1, 2);
        l0 = l0 * alpha0 + sum0;
        l1 = l1 * alpha1 + sum1;

        #pragma unroll
        for (int ni = 0; ni < 8; ni++) {
            accO[ni][0] *= alpha0; accO[ni][1] *= alpha0;
            accO[ni][2] *= alpha1; accO[ni][3] *= alpha1;
        }

        // Store P into A-frag layout (warp-private region => syncwarp only)
        {
            int r0 = lane >> 2;
            #pragma unroll
            for (int ni = 0; ni < 8; ni++) {
                #pragma unroll
                for (int v = 0; v < 4; v++) {
                    int r = (v < 2) ? r0 : (r0 + 8);
                    int c = ni * 8 + (lane & 3) * 2 + (v & 1);
                    int ip = ((warp * 8 + (c >> 3)) * 32 + ((r & 7) * 4 + (c & 3))) * 4
                             + (((r >> 3) & 1) + 2 * ((c >> 2) & 1));
                    Ps[ip] = f2tf(accS[ni][v]);
                }
            }
        }
        __syncwarp();

        // O += P @ V
        #pragma unroll
        for (int kt = 0; kt < 8; kt++) {
            uint4 afr = Ps4[(warp * 8 + kt) * 32 + lane];
            #pragma unroll
            for (int ni = 0; ni < 8; ni++) {
                uint2 bfr = Vt2[(ni * 8 + kt) * 32 + lane];
                mma_tf32(accO[ni], afr, bfr);
            }
        }
    }

    // Epilogue: normalize and write context
    float inv0 = 1.0f / l0;
    float inv1 = 1.0f / l1;
    int row0 = qbase + warp * 16 + (lane >> 2);
    #pragma unroll
    for (int ni = 0; ni < 8; ni++) {
        int col = ni * 8 + (lane & 3) * 2;
        float2 v0 = make_float2(accO[ni][0] * inv0, accO[ni][1] * inv0);
        float2 v1 = make_float2(accO[ni][2] * inv1, accO[ni][3] * inv1);
        *(float2*)&O[base + (size_t)row0 * K_D + col] = v0;
        *(float2*)&O[base + (size_t)(row0 + 8) * K_D + col] = v1;
    }
}

// ---------------------------------------------------------------------------
extern "C" void kernel_launch(void* const* d_in, const int* in_sizes, int n_in,
                              void* d_out, int out_size)
{
    const float* query = (const float*)d_in[0];
    const float* key   = (const float*)d_in[1];
    const float* value = (const float*)d_in[2];
    const float* Wq    = (const float*)d_in[3];
    const float* bq    = (const float*)d_in[4];
    const float* Wk    = (const float*)d_in[5];
    const float* bk    = (const float*)d_in[6];
    const float* Wv    = (const float*)d_in[7];
    const float* bv    = (const float*)d_in[8];
    const float* Wo    = (const float*)d_in[9];
    const float* bo    = (const float*)d_in[10];
    float* out = (float*)d_out;

    float *gq, *gk, *gv, *gc;
    cudaGetSymbolAddress((void**)&gq, g_Q);
    cudaGetSymbolAddress((void**)&gk, g_K);
    cudaGetSymbolAddress((void**)&gv, g_V);
    cudaGetSymbolAddress((void**)&gc, g_C);

    static bool attr_done = false;
    if (!attr_done) {
        cudaFuncSetAttribute(flash_tc, cudaFuncAttributeMaxDynamicSharedMemorySize,
                             24576 * sizeof(unsigned));
        attr_done = true;
    }

    dim3 gemm_grid(K_D / 128, K_ROWS / 128);   // (8, 64)
    gemm_tc<<<gemm_grid, 256>>>(query, Wq, bq, gq);
    gemm_tc<<<gemm_grid, 256>>>(key,   Wk, bk, gk);
    gemm_tc<<<gemm_grid, 256>>>(value, Wv, bv, gv);

    dim3 attn_grid(K_B * K_H, K_S / 128);      // (64, 16)
    flash_tc<<<attn_grid, 256, 24576 * sizeof(unsigned)>>>(gq, gk, gv, gc);

    gemm_tc<<<gemm_grid, 256>>>(gc, Wo, bo, out);
}